// round 1
// baseline (speedup 1.0000x reference)
#include <cuda_runtime.h>
#include <math.h>

// Problem constants
// B=128, T=64, IN=512, CTRL=512, N=128, MM=128, S=3, R=4, W=1
// L=134, LW=390, NOUT=926, K1=1024 (IN + R*MM), K2=512

// ---------------- persistent device state ----------------
__device__ float g_part1[4 * 128 * 512];   // gemm1 split-K partials [s][b][n]
__device__ float g_part2[2 * 128 * 926];   // gemm2 split-K partials [s][b][n]
__device__ float g_Mem[128 * 128 * 128];   // [b][n][m]
__device__ float g_rw[128 * 4 * 128];      // [b][r][n]
__device__ float g_ww[128 * 128];          // [b][n]
__device__ float g_rv[128 * 512];          // [b][r*128+m]

// ---------------- init ----------------
__global__ void init_kernel() {
    int i0 = blockIdx.x * blockDim.x + threadIdx.x;
    int st = gridDim.x * blockDim.x;
    for (int i = i0; i < 128 * 128 * 128; i += st) {
        int n = (i >> 7) & 127;
        g_Mem[i] = (n == 64) ? 1.0f : 0.0f;
    }
    for (int i = i0; i < 128 * 512; i += st) { g_rw[i] = 0.0f; g_rv[i] = 0.0f; }
    for (int i = i0; i < 128 * 128; i += st) { g_ww[i] = 0.0f; }
}

// ---------------- GEMM1: part1[s] = h @ Wc (K chunk s) ----------------
// h[b][k] = k<512 ? x[b][t][k] : rv[b][k-512]
// grid (16 coltiles, 2 rowtiles, 4 splits), 128 threads
// tile BM=64, BN=32, BK=16, K-chunk=256
__global__ void __launch_bounds__(128) gemm1_kernel(
    const float* __restrict__ x, const float* __restrict__ Wc, int t) {
    __shared__ float As[16 * 68];  // [k][row], padded
    __shared__ float Bs[16 * 32];  // [k][col]

    int tid = threadIdx.x;
    int col0 = blockIdx.x * 32;
    int row0 = blockIdx.y * 64;
    int k0b  = blockIdx.z * 256;

    int tr = tid >> 3;   // 0..15 -> rows tr*4..+3
    int tc = tid & 7;    // 0..7  -> cols tc*4..+3
    int a_k = tid & 15, a_r = tid >> 4;   // A load mapping
    int b_n = tid & 31, b_k = tid >> 5;   // B load mapping

    float acc[4][4] = {};

    for (int kt = 0; kt < 16; kt++) {
        int k0 = k0b + kt * 16;
#pragma unroll
        for (int p = 0; p < 8; p++) {
            int row = p * 8 + a_r;
            int grow = row0 + row;
            int gk = k0 + a_k;
            float v;
            if (gk < 512) v = x[(grow * 64 + t) * 512 + gk];
            else          v = g_rv[grow * 512 + (gk - 512)];
            As[a_k * 68 + row] = v;
        }
#pragma unroll
        for (int p = 0; p < 4; p++) {
            int kk = p * 4 + b_k;
            Bs[kk * 32 + b_n] = Wc[(k0 + kk) * 512 + col0 + b_n];
        }
        __syncthreads();
#pragma unroll
        for (int kk = 0; kk < 16; kk++) {
            float4 av = *(const float4*)&As[kk * 68 + tr * 4];
            float4 bv = *(const float4*)&Bs[kk * 32 + tc * 4];
            float ar[4] = {av.x, av.y, av.z, av.w};
            float br[4] = {bv.x, bv.y, bv.z, bv.w};
#pragma unroll
            for (int i = 0; i < 4; i++)
#pragma unroll
                for (int j = 0; j < 4; j++) acc[i][j] += ar[i] * br[j];
        }
        __syncthreads();
    }
    // store partials
#pragma unroll
    for (int i = 0; i < 4; i++) {
        int grow = row0 + tr * 4 + i;
        float4 v = make_float4(acc[i][0], acc[i][1], acc[i][2], acc[i][3]);
        *(float4*)&g_part1[(blockIdx.z * 128 + grow) * 512 + col0 + tc * 4] = v;
    }
}

// ---------------- GEMM2: part2[s] = tanh(sum(part1)+bc) @ Wk (K chunk s) ----------------
// also writes d_out (tanh activations) from coltile 0 CTAs
// grid (29 coltiles, 2 rowtiles, 2 splits), 128 threads; BM=64,BN=32,BK=16, chunk=256
__global__ void __launch_bounds__(128) gemm2_kernel(
    const float* __restrict__ bc, const float* __restrict__ Wk,
    float* __restrict__ dout, int t) {
    __shared__ float As[16 * 68];
    __shared__ float Bs[16 * 32];

    int tid = threadIdx.x;
    int col0 = blockIdx.x * 32;
    int row0 = blockIdx.y * 64;
    int k0b  = blockIdx.z * 256;

    int tr = tid >> 3;
    int tc = tid & 7;
    int a_k = tid & 15, a_r = tid >> 4;
    int b_n = tid & 31, b_k = tid >> 5;

    float acc[4][4] = {};

    for (int kt = 0; kt < 16; kt++) {
        int k0 = k0b + kt * 16;
#pragma unroll
        for (int p = 0; p < 8; p++) {
            int row = p * 8 + a_r;
            int grow = row0 + row;
            int gk = k0 + a_k;
            float s = g_part1[(0 * 128 + grow) * 512 + gk]
                    + g_part1[(1 * 128 + grow) * 512 + gk]
                    + g_part1[(2 * 128 + grow) * 512 + gk]
                    + g_part1[(3 * 128 + grow) * 512 + gk]
                    + bc[gk];
            float v = tanhf(s);
            if (blockIdx.x == 0) dout[(grow * 64 + t) * 512 + gk] = v;
            As[a_k * 68 + row] = v;
        }
#pragma unroll
        for (int p = 0; p < 4; p++) {
            int kk = p * 4 + b_k;
            int gc = col0 + b_n;
            Bs[kk * 32 + b_n] = (gc < 926) ? Wk[(k0 + kk) * 926 + gc] : 0.0f;
        }
        __syncthreads();
#pragma unroll
        for (int kk = 0; kk < 16; kk++) {
            float4 av = *(const float4*)&As[kk * 68 + tr * 4];
            float4 bv = *(const float4*)&Bs[kk * 32 + tc * 4];
            float ar[4] = {av.x, av.y, av.z, av.w};
            float br[4] = {bv.x, bv.y, bv.z, bv.w};
#pragma unroll
            for (int i = 0; i < 4; i++)
#pragma unroll
                for (int j = 0; j < 4; j++) acc[i][j] += ar[i] * br[j];
        }
        __syncthreads();
    }
#pragma unroll
    for (int i = 0; i < 4; i++) {
        int grow = row0 + tr * 4 + i;
#pragma unroll
        for (int j = 0; j < 4; j++) {
            int gc = col0 + tc * 4 + j;
            if (gc < 926)
                g_part2[(blockIdx.z * 128 + grow) * 926 + gc] = acc[i][j];
        }
    }
}

// ---------------- reductions (128 threads) ----------------
__device__ __forceinline__ float warpSum(float v) {
#pragma unroll
    for (int o = 16; o > 0; o >>= 1) v += __shfl_xor_sync(0xffffffffu, v, o);
    return v;
}
__device__ __forceinline__ float warpMax(float v) {
#pragma unroll
    for (int o = 16; o > 0; o >>= 1) v = fmaxf(v, __shfl_xor_sync(0xffffffffu, v, o));
    return v;
}
__device__ __forceinline__ float blockSum(float v, float* sc) {
    int lane = threadIdx.x & 31, wid = threadIdx.x >> 5;
    v = warpSum(v);
    __syncthreads();
    if (lane == 0) sc[wid] = v;
    __syncthreads();
    return sc[0] + sc[1] + sc[2] + sc[3];
}
__device__ __forceinline__ float blockMax(float v, float* sc) {
    int lane = threadIdx.x & 31, wid = threadIdx.x >> 5;
    v = warpMax(v);
    __syncthreads();
    if (lane == 0) sc[wid] = v;
    __syncthreads();
    return fmaxf(fmaxf(sc[0], sc[1]), fmaxf(sc[2], sc[3]));
}

// ---------------- heads + memory update kernel (1 CTA per batch b) ----------------
__global__ void __launch_bounds__(128) heads_kernel(const float* __restrict__ bk) {
    extern __shared__ float sM[];  // [128][129] padded memory tile
    __shared__ float s_instr[926];
    __shared__ float s_rsn[128];
    __shared__ float s_q[5][128];
    __shared__ float s_sim[5][128];
    __shared__ float s_wn[5][128];
    __shared__ float s_wi[128];
    __shared__ float s_hp[5][6];   // beta, g, s0, s1, s2, tpow
    __shared__ float s_red[4];

    int b = blockIdx.x;
    int tid = threadIdx.x;

    // instrs = sum of gemm2 partials + bk
    for (int j = tid; j < 926; j += 128)
        s_instr[j] = g_part2[b * 926 + j] + g_part2[(128 + b) * 926 + j] + bk[j];

    // load Mem[b] into smem (padded rows)
    const float* Mb = &g_Mem[b * 16384];
    for (int i = tid; i < 16384; i += 128) {
        int n = i >> 7, m = i & 127;
        sM[n * 129 + m] = Mb[i];
    }

    // per-head scalars
    if (tid < 5) {
        int base = (tid < 4) ? tid * 134 : 536;
        float beta = expf(s_instr[base + 128]);
        float g = 1.0f / (1.0f + expf(-s_instr[base + 129]));
        float a0 = s_instr[base + 130], a1 = s_instr[base + 131], a2 = s_instr[base + 132];
        float mx = fmaxf(a0, fmaxf(a1, a2));
        float e0 = expf(a0 - mx), e1 = expf(a1 - mx), e2 = expf(a2 - mx);
        float es = e0 + e1 + e2;
        float xt = s_instr[base + 133];
        float tpow = fmaxf(xt, 0.0f) + log1pf(expf(-fabsf(xt))) + 1.0f;  // softplus+1
        s_hp[tid][0] = beta; s_hp[tid][1] = g;
        s_hp[tid][2] = e0 / es; s_hp[tid][3] = e1 / es; s_hp[tid][4] = e2 / es;
        s_hp[tid][5] = tpow;
    }
    __syncthreads();

    // column norms of Mem over n: rsn[m] = rsqrt(max(sum_n M[n][m]^2, 1e-12))
    {
        float cs = 0.0f;
#pragma unroll 8
        for (int n = 0; n < 128; n++) {
            float v = sM[n * 129 + tid];
            cs += v * v;
        }
        s_rsn[tid] = rsqrtf(fmaxf(cs, 1e-12f));
    }
    __syncthreads();

    // q_h[m] = nk_h[m] * rsn[m]  (folds both normalizations into the matvec)
    for (int h = 0; h < 5; h++) {
        int base = (h < 4) ? h * 134 : 536;
        float k = s_instr[base + tid];
        float ks = blockSum(k * k, s_red);
        s_q[h][tid] = k * rsqrtf(fmaxf(ks, 1e-12f)) * s_rsn[tid];
    }
    __syncthreads();

    // sim_h[n] = sum_m M[n][m] * q_h[m]   (thread = n, 5 heads fused)
    {
        float a0 = 0, a1 = 0, a2 = 0, a3 = 0, a4 = 0;
        const float* row = &sM[tid * 129];
#pragma unroll 4
        for (int m = 0; m < 128; m++) {
            float v = row[m];
            a0 += v * s_q[0][m]; a1 += v * s_q[1][m]; a2 += v * s_q[2][m];
            a3 += v * s_q[3][m]; a4 += v * s_q[4][m];
        }
        s_sim[0][tid] = a0; s_sim[1][tid] = a1; s_sim[2][tid] = a2;
        s_sim[3][tid] = a3; s_sim[4][tid] = a4;
    }
    __syncthreads();

    // per head: softmax -> interpolate -> circular shift -> sharpen -> normalize
    for (int h = 0; h < 5; h++) {
        float beta = s_hp[h][0], g = s_hp[h][1];
        float sh0 = s_hp[h][2], sh1 = s_hp[h][3], sh2 = s_hp[h][4];
        float tpow = s_hp[h][5];

        float v = s_sim[h][tid] * beta;
        float mx = blockMax(v, s_red);
        float e = expf(v - mx);
        float se = blockSum(e, s_red);
        float wc = e / se;

        float wold = (h < 4) ? g_rw[(b * 4 + h) * 128 + tid] : g_ww[b * 128 + tid];
        float wi = wc * g + wold * (1.0f - g);
        __syncthreads();
        s_wi[tid] = wi;
        __syncthreads();
        float wsv = sh0 * s_wi[(tid + 127) & 127] + sh1 * s_wi[tid] + sh2 * s_wi[(tid + 1) & 127];
        float p = powf(wsv, tpow);
        float ps = blockSum(p, s_red);
        float wn = p / (ps + 1e-12f);
        s_wn[h][tid] = wn;
        if (h < 4) g_rw[(b * 4 + h) * 128 + tid] = wn;
        else       g_ww[b * 128 + tid] = wn;
    }
    __syncthreads();

    // erase/add (W=1) + rv = Mem_new^T @ rw_new   (thread = m)
    {
        float em = s_instr[536 + 134 + tid];
        float am = s_instr[536 + 262 + tid];
        float r0 = 0, r1 = 0, r2 = 0, r3 = 0;
#pragma unroll 4
        for (int n = 0; n < 128; n++) {
            float wwn = s_wn[4][n];
            float Mv = sM[n * 129 + tid];
            Mv = Mv * (1.0f - wwn * em) + wwn * am;
            sM[n * 129 + tid] = Mv;
            r0 += Mv * s_wn[0][n];
            r1 += Mv * s_wn[1][n];
            r2 += Mv * s_wn[2][n];
            r3 += Mv * s_wn[3][n];
        }
        g_rv[b * 512 +   0 + tid] = r0;
        g_rv[b * 512 + 128 + tid] = r1;
        g_rv[b * 512 + 256 + tid] = r2;
        g_rv[b * 512 + 384 + tid] = r3;
    }
    __syncthreads();

    // write Mem back
    float* Mbw = &g_Mem[b * 16384];
    for (int i = tid; i < 16384; i += 128) {
        int n = i >> 7, m = i & 127;
        Mbw[i] = sM[n * 129 + m];
    }
}

// ---------------- launch ----------------
extern "C" void kernel_launch(void* const* d_in, const int* in_sizes, int n_in,
                              void* d_out, int out_size) {
    const float *x = nullptr, *Wc = nullptr, *bc = nullptr, *Wk = nullptr, *bk = nullptr;
    for (int i = 0; i < n_in; i++) {
        switch (in_sizes[i]) {
            case 128 * 64 * 512: x  = (const float*)d_in[i]; break;  // 4194304
            case 1024 * 512:     Wc = (const float*)d_in[i]; break;  // 524288
            case 512:            bc = (const float*)d_in[i]; break;
            case 512 * 926:      Wk = (const float*)d_in[i]; break;  // 474112
            case 926:            bk = (const float*)d_in[i]; break;
        }
    }

    const int HEADS_SMEM = 128 * 129 * 4;  // 66048 B dynamic
    cudaFuncSetAttribute(heads_kernel, cudaFuncAttributeMaxDynamicSharedMemorySize, HEADS_SMEM);

    init_kernel<<<256, 256>>>();
    for (int t = 0; t < 64; t++) {
        gemm1_kernel<<<dim3(16, 2, 4), 128>>>(x, Wc, t);
        gemm2_kernel<<<dim3(29, 2, 2), 128>>>(bc, Wk, (float*)d_out, t);
        heads_kernel<<<128, 128, HEADS_SMEM>>>(bk);
    }
}

// round 2
// speedup vs baseline: 2.3203x; 2.3203x over previous
#include <cuda_runtime.h>
#include <math.h>

// B=128, T=64, IN=512, CTRL=512, N=128, MM=128, S=3, R=4, W=1
// L=134, LW=390, NOUT=926, K1=1024, K2=512
#define NB 128u

// ---------------- persistent device state ----------------
__device__ float g_part1[8 * 128 * 512];   // gemm1 split-K partials [s][b][n]
__device__ float g_part2[4 * 128 * 928];   // gemm2 split-K partials [s][b][col] (padded 928)
__device__ float g_act[128 * 512];         // tanh activations
__device__ float g_rv[128 * 512];          // read vectors [b][r*128+m]
__device__ unsigned g_barrier;

// ---------------- init (runs each graph replay) ----------------
__global__ void init_kernel() {
    int i = blockIdx.x * blockDim.x + threadIdx.x;
    int st = gridDim.x * blockDim.x;
    for (int j = i; j < 128 * 512; j += st) g_rv[j] = 0.0f;
    if (i == 0) g_barrier = 0u;
}

// ---------------- gpu-scope grid barrier ----------------
__device__ __forceinline__ void grid_sync(unsigned target) {
    __syncthreads();
    if (threadIdx.x == 0) {
        unsigned* bar = &g_barrier;
        asm volatile("red.release.gpu.add.u32 [%0], 1;" :: "l"(bar) : "memory");
        unsigned v;
        do {
            asm volatile("ld.acquire.gpu.b32 %0, [%1];" : "=r"(v) : "l"(bar) : "memory");
        } while (v < target);
    }
    __syncthreads();
}

// ---------------- block reductions (8 warps) ----------------
__device__ __forceinline__ float blockSum(float v, float* s_red) {
#pragma unroll
    for (int o = 16; o > 0; o >>= 1) v += __shfl_xor_sync(0xffffffffu, v, o);
    if ((threadIdx.x & 31) == 0) s_red[threadIdx.x >> 5] = v;
    __syncthreads();
    float r = s_red[0];
#pragma unroll
    for (int i = 1; i < 8; i++) r += s_red[i];
    __syncthreads();
    return r;
}
__device__ __forceinline__ float blockMax(float v, float* s_red) {
#pragma unroll
    for (int o = 16; o > 0; o >>= 1) v = fmaxf(v, __shfl_xor_sync(0xffffffffu, v, o));
    if ((threadIdx.x & 31) == 0) s_red[threadIdx.x >> 5] = v;
    __syncthreads();
    float r = s_red[0];
#pragma unroll
    for (int i = 1; i < 8; i++) r = fmaxf(r, s_red[i]);
    __syncthreads();
    return r;
}

// ---------------- the persistent kernel ----------------
__global__ void __launch_bounds__(256) ntm_persistent(
    const float* __restrict__ x, const float* __restrict__ Wc,
    const float* __restrict__ bc, const float* __restrict__ Wk,
    const float* __restrict__ bk, float* __restrict__ dout) {
    extern __shared__ float smem[];
    float* sM = smem;                   // 128*129 = 16512 (Mem, persistent)
    float* s_w = smem + 16512;          // 5*128   = 640   (rw[4], ww[1], persistent)
    float* scratch = smem + 17152;      // 4224 floats, phase-unioned

    const int tid = threadIdx.x;
    const int e = blockIdx.x;           // CTA id == batch id in act/heads phases

    // per-CTA state init
    for (int i = tid; i < 128 * 128; i += 256) {
        int n = i >> 7, m = i & 127;
        sM[n * 129 + m] = (n == 64) ? 1.0f : 0.0f;
    }
    for (int i = tid; i < 640; i += 256) s_w[i] = 0.0f;
    __syncthreads();

    // GEMM tile coordinates
    const int g1_row0 = ((e >> 3) >> 3) * 64;   // tile = e>>3 (16 tiles), split = e&7
    const int g1_col0 = ((e >> 3) & 7) * 64;
    const int g1_k0   = (e & 7) * 128;
    const int g2_tile = e >> 2, g2_split = e & 3;  // 30 tiles x 4 splits (e<120)
    const int g2_row0 = (g2_tile / 15) * 64;
    const int g2_col0 = (g2_tile % 15) * 64;
    const int g2_k0   = g2_split * 128;

    float* As = scratch;          // 32 x 68
    float* Bs = scratch + 2176;   // 32 x 64

    const int tr = tid >> 4, tc = tid & 15;       // micro-tile coords
    const int arow = tid & 63, aq = tid >> 6;     // A staging coords

    unsigned nsync = 0;

    for (int t = 0; t < 64; t++) {
        // =========== GEMM1: part1 = h @ Wc (h = [x_t | rv]) ===========
        {
            // k-slice [g1_k0, g1_k0+128) lies entirely in x (k<512) or rv (k>=512)
            const float* Asrc;
            size_t a_rstride;
            if (g1_k0 < 512) { Asrc = x + (size_t)t * 512 + g1_k0; a_rstride = 64 * 512; }
            else             { Asrc = g_rv + (g1_k0 - 512);        a_rstride = 512; }

            float acc[4][4];
#pragma unroll
            for (int i = 0; i < 4; i++)
#pragma unroll
                for (int j = 0; j < 4; j++) acc[i][j] = 0.0f;

            for (int ch = 0; ch < 4; ch++) {
                int kc = ch * 32;  // offset within slice
#pragma unroll
                for (int u = 0; u < 2; u++) {
                    int kq = (aq + u * 4) * 4;
                    float4 v = *(const float4*)&Asrc[(size_t)(g1_row0 + arow) * a_rstride + kc + kq];
                    As[(kq + 0) * 68 + arow] = v.x;
                    As[(kq + 1) * 68 + arow] = v.y;
                    As[(kq + 2) * 68 + arow] = v.z;
                    As[(kq + 3) * 68 + arow] = v.w;
                }
#pragma unroll
                for (int u = 0; u < 2; u++) {
                    int kk = (tid >> 4) + u * 16;
                    *(float4*)&Bs[kk * 64 + tc * 4] =
                        *(const float4*)&Wc[(size_t)(g1_k0 + kc + kk) * 512 + g1_col0 + tc * 4];
                }
                __syncthreads();
#pragma unroll
                for (int kk = 0; kk < 32; kk++) {
                    float4 a4 = *(const float4*)&As[kk * 68 + tr * 4];
                    float4 b4 = *(const float4*)&Bs[kk * 64 + tc * 4];
                    float ar[4] = {a4.x, a4.y, a4.z, a4.w};
                    float br[4] = {b4.x, b4.y, b4.z, b4.w};
#pragma unroll
                    for (int i = 0; i < 4; i++)
#pragma unroll
                        for (int j = 0; j < 4; j++) acc[i][j] += ar[i] * br[j];
                }
                __syncthreads();
            }
#pragma unroll
            for (int i = 0; i < 4; i++) {
                *(float4*)&g_part1[(size_t)((e & 7) * 128 + g1_row0 + tr * 4 + i) * 512 + g1_col0 + tc * 4] =
                    make_float4(acc[i][0], acc[i][1], acc[i][2], acc[i][3]);
            }
        }
        grid_sync(++nsync * NB);

        // =========== ACT: tanh(sum partials + bc), write d_out ===========
        {
            for (int j = tid; j < 512; j += 256) {
                float s = bc[j];
#pragma unroll
                for (int sp = 0; sp < 8; sp++) s += g_part1[(size_t)(sp * 128 + e) * 512 + j];
                float v = tanhf(s);
                g_act[e * 512 + j] = v;
                dout[((size_t)e * 64 + t) * 512 + j] = v;
            }
        }
        grid_sync(++nsync * NB);

        // =========== GEMM2: part2 = act @ Wk ===========
        if (e < 120) {
            float acc[4][4];
#pragma unroll
            for (int i = 0; i < 4; i++)
#pragma unroll
                for (int j = 0; j < 4; j++) acc[i][j] = 0.0f;

            for (int ch = 0; ch < 4; ch++) {
                int kc = g2_k0 + ch * 32;
#pragma unroll
                for (int u = 0; u < 2; u++) {
                    int kq = (aq + u * 4) * 4;
                    float4 v = *(const float4*)&g_act[(size_t)(g2_row0 + arow) * 512 + kc + kq];
                    As[(kq + 0) * 68 + arow] = v.x;
                    As[(kq + 1) * 68 + arow] = v.y;
                    As[(kq + 2) * 68 + arow] = v.z;
                    As[(kq + 3) * 68 + arow] = v.w;
                }
                {
                    int kk = tid >> 3;
                    int c8 = (tid & 7) * 8;
#pragma unroll
                    for (int j = 0; j < 8; j++) {
                        int gc = g2_col0 + c8 + j;
                        Bs[kk * 64 + c8 + j] = (gc < 926) ? Wk[(size_t)(kc + kk) * 926 + gc] : 0.0f;
                    }
                }
                __syncthreads();
#pragma unroll
                for (int kk = 0; kk < 32; kk++) {
                    float4 a4 = *(const float4*)&As[kk * 68 + tr * 4];
                    float4 b4 = *(const float4*)&Bs[kk * 64 + tc * 4];
                    float ar[4] = {a4.x, a4.y, a4.z, a4.w};
                    float br[4] = {b4.x, b4.y, b4.z, b4.w};
#pragma unroll
                    for (int i = 0; i < 4; i++)
#pragma unroll
                        for (int j = 0; j < 4; j++) acc[i][j] += ar[i] * br[j];
                }
                __syncthreads();
            }
#pragma unroll
            for (int i = 0; i < 4; i++)
#pragma unroll
                for (int j = 0; j < 4; j++) {
                    int gc = g2_col0 + tc * 4 + j;
                    if (gc < 926)
                        g_part2[(size_t)(g2_split * 128 + g2_row0 + tr * 4 + i) * 928 + gc] = acc[i][j];
                }
        }
        grid_sync(++nsync * NB);

        // =========== HEADS: all per-batch head math + Mem update (SMEM-resident) ===========
        {
            float* s_instr = scratch;          // 928
            float* s_rsn   = scratch + 928;    // 128
            float* s_q     = scratch + 1056;   // 5*128
            float* s_p2    = scratch + 1696;   // 5*256 (pair partials)
            float* s_wi    = scratch + 2976;   // 128
            float* s_hp    = scratch + 3104;   // 5*8
            float* s_red   = scratch + 3144;   // 8

            // instr = sum of gemm2 partials + bk
            for (int j = tid; j < 926; j += 256) {
                float s = bk[j];
#pragma unroll
                for (int sp = 0; sp < 4; sp++) s += g_part2[(size_t)(sp * 128 + e) * 928 + j];
                s_instr[j] = s;
            }
            // column-norm partials (independent of s_instr)
            {
                int m = tid & 127, half = tid >> 7;
                float cs = 0.0f;
                int n0 = half * 64;
#pragma unroll 8
                for (int n = n0; n < n0 + 64; n++) { float v = sM[n * 129 + m]; cs += v * v; }
                s_p2[half * 128 + m] = cs;
            }
            __syncthreads();
            if (tid < 128) s_rsn[tid] = rsqrtf(fmaxf(s_p2[tid] + s_p2[128 + tid], 1e-12f));
            if (tid < 5) {
                int base = (tid < 4) ? tid * 134 : 536;
                float beta = expf(s_instr[base + 128]);
                float gg = 1.0f / (1.0f + expf(-s_instr[base + 129]));
                float a0 = s_instr[base + 130], a1 = s_instr[base + 131], a2 = s_instr[base + 132];
                float mx = fmaxf(a0, fmaxf(a1, a2));
                float e0 = expf(a0 - mx), e1 = expf(a1 - mx), e2 = expf(a2 - mx);
                float es = e0 + e1 + e2;
                float xt = s_instr[base + 133];
                float tpow = fmaxf(xt, 0.0f) + log1pf(expf(-fabsf(xt))) + 1.0f;
                s_hp[tid * 8 + 0] = beta; s_hp[tid * 8 + 1] = gg;
                s_hp[tid * 8 + 2] = e0 / es; s_hp[tid * 8 + 3] = e1 / es; s_hp[tid * 8 + 4] = e2 / es;
                s_hp[tid * 8 + 5] = tpow;
            }
            __syncthreads();
            // q_h[m] = l2n(key)[m] * rsn[m]
            for (int h = 0; h < 5; h++) {
                int base = (h < 4) ? h * 134 : 536;
                float kv = (tid < 128) ? s_instr[base + tid] : 0.0f;
                float ks = blockSum(kv * kv, s_red);
                if (tid < 128) s_q[h * 128 + tid] = kv * rsqrtf(fmaxf(ks, 1e-12f)) * s_rsn[tid];
            }
            __syncthreads();
            // sim partials: thread (n, half) over m range
            {
                int n = tid & 127, half = tid >> 7;
                const float* row = &sM[n * 129];
                int m0 = half * 64;
                float a0 = 0, a1 = 0, a2 = 0, a3 = 0, a4 = 0;
#pragma unroll 4
                for (int m = m0; m < m0 + 64; m++) {
                    float v = row[m];
                    a0 += v * s_q[m];       a1 += v * s_q[128 + m]; a2 += v * s_q[256 + m];
                    a3 += v * s_q[384 + m]; a4 += v * s_q[512 + m];
                }
                s_p2[0 * 256 + half * 128 + n] = a0;
                s_p2[1 * 256 + half * 128 + n] = a1;
                s_p2[2 * 256 + half * 128 + n] = a2;
                s_p2[3 * 256 + half * 128 + n] = a3;
                s_p2[4 * 256 + half * 128 + n] = a4;
            }
            __syncthreads();
            // per head: softmax -> interpolate -> shift -> sharpen -> normalize
            for (int h = 0; h < 5; h++) {
                float beta = s_hp[h * 8 + 0], gg = s_hp[h * 8 + 1];
                float sh0 = s_hp[h * 8 + 2], sh1 = s_hp[h * 8 + 3], sh2 = s_hp[h * 8 + 4];
                float tpow = s_hp[h * 8 + 5];

                float v = (tid < 128) ? (s_p2[h * 256 + tid] + s_p2[h * 256 + 128 + tid]) * beta
                                      : -3.4e38f;
                float mx = blockMax(v, s_red);
                float ee = (tid < 128) ? expf(v - mx) : 0.0f;
                float se = blockSum(ee, s_red);
                if (tid < 128) {
                    float wc = ee / se;
                    float wold = s_w[h * 128 + tid];
                    s_wi[tid] = wc * gg + wold * (1.0f - gg);
                }
                __syncthreads();
                float p = 0.0f;
                if (tid < 128) {
                    float wsv = sh0 * s_wi[(tid + 127) & 127] + sh1 * s_wi[tid] + sh2 * s_wi[(tid + 1) & 127];
                    p = powf(wsv, tpow);
                }
                float ps = blockSum(p, s_red);
                if (tid < 128) s_w[h * 128 + tid] = p / (ps + 1e-12f);
                __syncthreads();
            }
            // erase/add (W=1) + rv partials
            {
                int m = tid & 127, half = tid >> 7;
                float em = s_instr[670 + m];   // 536 + 134 + m
                float am = s_instr[798 + m];   // 536 + 262 + m
                float r0 = 0, r1 = 0, r2 = 0, r3 = 0;
                int n0 = half * 64;
#pragma unroll 4
                for (int n = n0; n < n0 + 64; n++) {
                    float wwn = s_w[512 + n];
                    float Mv = sM[n * 129 + m];
                    Mv = Mv * (1.0f - wwn * em) + wwn * am;
                    sM[n * 129 + m] = Mv;
                    r0 += Mv * s_w[n];       r1 += Mv * s_w[128 + n];
                    r2 += Mv * s_w[256 + n]; r3 += Mv * s_w[384 + n];
                }
                s_p2[0 * 256 + half * 128 + m] = r0;
                s_p2[1 * 256 + half * 128 + m] = r1;
                s_p2[2 * 256 + half * 128 + m] = r2;
                s_p2[3 * 256 + half * 128 + m] = r3;
            }
            __syncthreads();
            if (tid < 128) {
#pragma unroll
                for (int r = 0; r < 4; r++)
                    g_rv[e * 512 + r * 128 + tid] = s_p2[r * 256 + tid] + s_p2[r * 256 + 128 + tid];
            }
        }
        grid_sync(++nsync * NB);
    }
}

// ---------------- launch ----------------
extern "C" void kernel_launch(void* const* d_in, const int* in_sizes, int n_in,
                              void* d_out, int out_size) {
    const float *x = nullptr, *Wc = nullptr, *bc = nullptr, *Wk = nullptr, *bk = nullptr;
    for (int i = 0; i < n_in; i++) {
        switch (in_sizes[i]) {
            case 128 * 64 * 512: x  = (const float*)d_in[i]; break;
            case 1024 * 512:     Wc = (const float*)d_in[i]; break;
            case 512:            bc = (const float*)d_in[i]; break;
            case 512 * 926:      Wk = (const float*)d_in[i]; break;
            case 926:            bk = (const float*)d_in[i]; break;
        }
    }

    const int SMEM = (16512 + 640 + 4224) * 4;  // 85504 B
    cudaFuncSetAttribute(ntm_persistent, cudaFuncAttributeMaxDynamicSharedMemorySize, SMEM);

    init_kernel<<<128, 256>>>();
    ntm_persistent<<<128, 256, SMEM>>>(x, Wc, bc, Wk, bk, (float*)d_out);
}

// round 5
// speedup vs baseline: 4.0961x; 1.7654x over previous
#include <cuda_runtime.h>
#include <cuda_bf16.h>
#include <math.h>
#include <stdint.h>

// B=128, T=64, IN=512, CTRL=512, N=128, MM=128, S=3, R=4, W=1
// L=134, LW=390, NOUT=926, K1=1024, K2=512
#define NB 128u

// ---------------- persistent device state ----------------
__device__ float g_part1[16 * 128 * 512];                       // gemm1 partials [split][b][col]
__device__ float g_part2[8 * 128 * 960];                        // gemm2 partials [split][b][col]
__device__ __align__(16) __nv_bfloat16 g_xh[128 * 64 * 512];    // x split-bf16
__device__ __align__(16) __nv_bfloat16 g_xl[128 * 64 * 512];
__device__ __align__(16) __nv_bfloat16 g_WcT_h[512 * 1024];     // Wc^T [n][k]
__device__ __align__(16) __nv_bfloat16 g_WcT_l[512 * 1024];
__device__ __align__(16) __nv_bfloat16 g_WkT_h[960 * 512];      // Wk^T [n][k], rows>=926 zero
__device__ __align__(16) __nv_bfloat16 g_WkT_l[960 * 512];
__device__ __align__(16) __nv_bfloat16 g_acth[128 * 512];       // tanh activations split-bf16
__device__ __align__(16) __nv_bfloat16 g_actl[128 * 512];
__device__ __align__(16) __nv_bfloat16 g_rvh[128 * 512];        // read vectors split-bf16
__device__ __align__(16) __nv_bfloat16 g_rvl[128 * 512];
__device__ unsigned g_barrier;

// ---------------- helpers ----------------
__device__ __forceinline__ uint32_t smem_u32(const void* p) {
    uint32_t a;
    asm("{ .reg .u64 t; cvta.to.shared.u64 t, %1; cvt.u32.u64 %0, t; }" : "=r"(a) : "l"(p));
    return a;
}
__device__ __forceinline__ void ldmatrix_x4(uint32_t& r0, uint32_t& r1, uint32_t& r2, uint32_t& r3, uint32_t addr) {
    asm volatile("ldmatrix.sync.aligned.m8n8.x4.shared.b16 {%0,%1,%2,%3}, [%4];"
                 : "=r"(r0), "=r"(r1), "=r"(r2), "=r"(r3) : "r"(addr));
}
__device__ __forceinline__ void mma_bf16(float* c, uint32_t a0, uint32_t a1, uint32_t a2, uint32_t a3,
                                         uint32_t b0, uint32_t b1) {
    asm volatile("mma.sync.aligned.m16n8k16.row.col.f32.bf16.bf16.f32 "
                 "{%0,%1,%2,%3}, {%4,%5,%6,%7}, {%8,%9}, {%0,%1,%2,%3};"
                 : "+f"(c[0]), "+f"(c[1]), "+f"(c[2]), "+f"(c[3])
                 : "r"(a0), "r"(a1), "r"(a2), "r"(a3), "r"(b0), "r"(b1));
}
static __device__ __forceinline__ void bf16_split(float v, __nv_bfloat16& h, __nv_bfloat16& l) {
    h = __float2bfloat16(v);
    l = __float2bfloat16(v - __bfloat162float(h));
}

// ---------------- prep kernels (run each replay) ----------------
__global__ void prep_x_kernel(const float* __restrict__ x) {
    int i = blockIdx.x * blockDim.x + threadIdx.x;
    int st = gridDim.x * blockDim.x;
    for (int j = i; j < 128 * 64 * 512; j += st) {
        __nv_bfloat16 h, l; bf16_split(x[j], h, l);
        g_xh[j] = h; g_xl[j] = l;
    }
    for (int j = i; j < 128 * 512; j += st) {
        g_rvh[j] = __float2bfloat16(0.0f);
        g_rvl[j] = __float2bfloat16(0.0f);
    }
    if (i == 0) g_barrier = 0u;
}
__global__ void prep_w_kernel(const float* __restrict__ Wc, const float* __restrict__ Wk) {
    int i = blockIdx.x * blockDim.x + threadIdx.x;
    int st = gridDim.x * blockDim.x;
    for (int j = i; j < 512 * 1024; j += st) {
        int n = j >> 10, k = j & 1023;
        __nv_bfloat16 h, l; bf16_split(Wc[k * 512 + n], h, l);
        g_WcT_h[j] = h; g_WcT_l[j] = l;
    }
    for (int j = i; j < 960 * 512; j += st) {
        int n = j >> 9, k = j & 511;
        float v = (n < 926) ? Wk[k * 926 + n] : 0.0f;
        __nv_bfloat16 h, l; bf16_split(v, h, l);
        g_WkT_h[j] = h; g_WkT_l[j] = l;
    }
}

// ---------------- gpu-scope grid barrier ----------------
__device__ __forceinline__ void grid_sync(unsigned target) {
    __syncthreads();
    if (threadIdx.x == 0) {
        unsigned* bar = &g_barrier;
        asm volatile("red.release.gpu.add.u32 [%0], 1;" :: "l"(bar) : "memory");
        unsigned v;
        do {
            asm volatile("ld.acquire.gpu.b32 %0, [%1];" : "=r"(v) : "l"(bar) : "memory");
        } while (v < target);
    }
    __syncthreads();
}

// ---------------- tile staging (row stride 144 B = 72 bf16; 8 quads of 16B per row) ----------------
__device__ __forceinline__ void stage_A144(const __nv_bfloat16* __restrict__ srcH,
                                           const __nv_bfloat16* __restrict__ srcL,
                                           size_t rstride, char* tAh, char* tAl, int tid) {
#pragma unroll
    for (int it = 0; it < 4; it++) {
        int q = tid + it * 256;            // 0..1023
        int r = q >> 3, qq = q & 7;        // 128 rows x 8 quads
        uint4 vh = *(const uint4*)((const char*)(srcH + (size_t)r * rstride) + qq * 16);
        uint4 vl = *(const uint4*)((const char*)(srcL + (size_t)r * rstride) + qq * 16);
        *(uint4*)(tAh + r * 144 + qq * 16) = vh;
        *(uint4*)(tAl + r * 144 + qq * 16) = vl;
    }
}
__device__ __forceinline__ void stage_B144(const __nv_bfloat16* __restrict__ srcH,
                                           const __nv_bfloat16* __restrict__ srcL,
                                           size_t rstride, char* tBh, char* tBl, int tid) {
#pragma unroll
    for (int it = 0; it < 2; it++) {
        int q = tid + it * 256;            // 0..511
        int r = q >> 3, qq = q & 7;        // 64 rows x 8 quads
        uint4 vh = *(const uint4*)((const char*)(srcH + (size_t)r * rstride) + qq * 16);
        uint4 vl = *(const uint4*)((const char*)(srcL + (size_t)r * rstride) + qq * 16);
        *(uint4*)(tBh + r * 144 + qq * 16) = vh;
        *(uint4*)(tBl + r * 144 + qq * 16) = vl;
    }
}

// ---------------- HMMA 128x64 tile, K=64, 3 passes (hh, lh, hl) ----------------
__device__ __forceinline__ void gemm_tile_hmma(
    uint32_t aAh, uint32_t aAl, uint32_t aBh, uint32_t aBl,
    float* __restrict__ dst, int ldw, int lane, int wid) {
    float acc[32];
#pragma unroll
    for (int i = 0; i < 32; i++) acc[i] = 0.0f;

    const int warp_m = wid * 16;
    const uint32_t aOff = (uint32_t)(warp_m + (lane & 15)) * 144u + (uint32_t)((lane >> 4) * 16);
    const int l8 = lane & 7, sel = lane >> 3;
    const uint32_t bOff = (uint32_t)(l8 + ((sel >> 1) * 8)) * 144u + (uint32_t)((sel & 1) * 16);

#pragma unroll
    for (int p = 0; p < 3; p++) {
        uint32_t aA = (p == 1) ? aAl : aAh;
        uint32_t aB = (p == 2) ? aBl : aBh;
#pragma unroll
        for (int ks = 0; ks < 4; ks++) {
            uint32_t a0, a1, a2, a3;
            ldmatrix_x4(a0, a1, a2, a3, aA + aOff + ks * 32);
#pragma unroll
            for (int np = 0; np < 4; np++) {
                uint32_t b0, b1, b2, b3;
                ldmatrix_x4(b0, b1, b2, b3, aB + bOff + np * (16 * 144) + ks * 32);
                mma_bf16(&acc[np * 8 + 0], a0, a1, a2, a3, b0, b1);
                mma_bf16(&acc[np * 8 + 4], a0, a1, a2, a3, b2, b3);
            }
        }
    }
    const int row = warp_m + (lane >> 2);
    const int colb = (lane & 3) * 2;
#pragma unroll
    for (int nf = 0; nf < 8; nf++) {
        int col = nf * 8 + colb;
        *(float2*)&dst[(size_t)row * ldw + col] = make_float2(acc[nf * 4 + 0], acc[nf * 4 + 1]);
        *(float2*)&dst[(size_t)(row + 8) * ldw + col] = make_float2(acc[nf * 4 + 2], acc[nf * 4 + 3]);
    }
}

// ---------------- the persistent kernel ----------------
__global__ void __launch_bounds__(256) ntm_persistent(
    const float* __restrict__ bc, const float* __restrict__ bk,
    float* __restrict__ dout) {
    extern __shared__ float smem[];
    float* sM  = smem;            // 16512 floats (Mem, persistent)
    float* s_w = smem + 16512;    // 640 floats (rw[4], ww[1], persistent)

    uint32_t base_u32 = smem_u32(smem);
    uint32_t tiles_u32 = (base_u32 + 17152u * 4u + 1023u) & ~1023u;
    char* tiles = (char*)smem + (tiles_u32 - base_u32);
    char* tAh = tiles;              uint32_t aAh = tiles_u32;
    char* tAl = tiles + 18432;      uint32_t aAl = tiles_u32 + 18432;
    char* tBh = tiles + 36864;      uint32_t aBh = tiles_u32 + 36864;
    char* tBl = tiles + 46080;      uint32_t aBl = tiles_u32 + 46080;
    float* scratch = (float*)tiles; // heads-phase scratch (aliases tiles, 13824 floats)

    const int tid = threadIdx.x;
    const int wid = tid >> 5, lane = tid & 31;
    const int e = blockIdx.x;

    // per-CTA state init
    for (int i = tid; i < 128 * 128; i += 256) {
        int n = i >> 7, m = i & 127;
        sM[n * 129 + m] = (n == 64) ? 1.0f : 0.0f;
    }
    for (int i = tid; i < 640; i += 256) s_w[i] = 0.0f;
    __syncthreads();

    // tile coordinates
    const int g1_n0 = (e & 7) * 64;          // 8 coltiles
    const int g1_sp = e >> 3;                // 16 K-splits (K slice 64)
    const int g1_k0 = g1_sp * 64;
    const int g2_n0 = (e % 15) * 64;         // 15 coltiles (960)
    const int g2_sp = e / 15;                // 8 K-splits
    const int g2_k0 = g2_sp * 64;

    unsigned nsync = 0;

    for (int t = 0; t < 64; t++) {
        // =========== GEMM1 (HMMA): part1 = [x_t | rv] @ Wc ===========
        {
            const __nv_bfloat16 *ah, *al;
            size_t rs;
            if (g1_k0 < 512) { ah = g_xh + (size_t)t * 512 + g1_k0; al = g_xl + (size_t)t * 512 + g1_k0; rs = 64 * 512; }
            else             { ah = g_rvh + (g1_k0 - 512);          al = g_rvl + (g1_k0 - 512);          rs = 512; }
            stage_A144(ah, al, rs, tAh, tAl, tid);
            stage_B144(g_WcT_h + (size_t)g1_n0 * 1024 + g1_k0, g_WcT_l + (size_t)g1_n0 * 1024 + g1_k0,
                       1024, tBh, tBl, tid);
            __syncthreads();
            gemm_tile_hmma(aAh, aAl, aBh, aBl,
                           &g_part1[(size_t)(g1_sp * 128) * 512 + g1_n0], 512, lane, wid);
        }
        grid_sync(++nsync * NB);

        // =========== ACT: tanh(sum 16 partials + bc) ===========
        {
            for (int j = tid; j < 512; j += 256) {
                float s = bc[j];
#pragma unroll
                for (int sp = 0; sp < 16; sp++) s += g_part1[(size_t)(sp * 128 + e) * 512 + j];
                float v = tanhf(s);
                dout[((size_t)e * 64 + t) * 512 + j] = v;
                __nv_bfloat16 h, l; bf16_split(v, h, l);
                g_acth[e * 512 + j] = h;
                g_actl[e * 512 + j] = l;
            }
        }
        grid_sync(++nsync * NB);

        // =========== GEMM2 (HMMA): part2 = act @ Wk ===========
        if (e < 120) {
            stage_A144(g_acth + g2_k0, g_actl + g2_k0, 512, tAh, tAl, tid);
            stage_B144(g_WkT_h + (size_t)g2_n0 * 512 + g2_k0, g_WkT_l + (size_t)g2_n0 * 512 + g2_k0,
                       512, tBh, tBl, tid);
            __syncthreads();
            gemm_tile_hmma(aAh, aAl, aBh, aBl,
                           &g_part2[(size_t)(g2_sp * 128) * 960 + g2_n0], 960, lane, wid);
        }
        grid_sync(++nsync * NB);

        // =========== HEADS (per-batch, SMEM-resident Mem, warp-per-head) ===========
        {
            float* s_instr = scratch;           // 928
            float* s_cn    = scratch + 928;     // 256
            float* s_rsn   = scratch + 1184;    // 128
            float* s_q     = scratch + 1312;    // 640
            float* s_p2    = scratch + 1952;    // 1280
            float* s_wi    = scratch + 3232;    // 640

            for (int j = tid; j < 926; j += 256) {
                float s = bk[j];
#pragma unroll
                for (int sp = 0; sp < 8; sp++) s += g_part2[(size_t)(sp * 128 + e) * 960 + j];
                s_instr[j] = s;
            }
            {
                int m = tid & 127, half = tid >> 7;
                float cs = 0.0f;
                int n0 = half * 64;
#pragma unroll 8
                for (int n = n0; n < n0 + 64; n++) { float v = sM[n * 129 + m]; cs += v * v; }
                s_cn[half * 128 + m] = cs;
            }
            __syncthreads();
            if (tid < 128) s_rsn[tid] = rsqrtf(fmaxf(s_cn[tid] + s_cn[128 + tid], 1e-12f));
            __syncthreads();

            // key l2-norm + q (warp h = head h)
            if (wid < 5) {
                int basei = (wid < 4) ? wid * 134 : 536;
                float kv[4];
                float ks = 0.0f;
#pragma unroll
                for (int j = 0; j < 4; j++) { int m = lane * 4 + j; kv[j] = s_instr[basei + m]; ks += kv[j] * kv[j]; }
#pragma unroll
                for (int o = 16; o > 0; o >>= 1) ks += __shfl_xor_sync(0xffffffffu, ks, o);
                float rk = rsqrtf(fmaxf(ks, 1e-12f));
#pragma unroll
                for (int j = 0; j < 4; j++) { int m = lane * 4 + j; s_q[wid * 128 + m] = kv[j] * rk * s_rsn[m]; }
            }
            __syncthreads();

            // sim matvec (all 256 threads)
            {
                int n = tid & 127, half = tid >> 7;
                const float* row = &sM[n * 129];
                int m0 = half * 64;
                float a0 = 0, a1 = 0, a2 = 0, a3 = 0, a4 = 0;
#pragma unroll 4
                for (int m = m0; m < m0 + 64; m++) {
                    float v = row[m];
                    a0 += v * s_q[m];       a1 += v * s_q[128 + m]; a2 += v * s_q[256 + m];
                    a3 += v * s_q[384 + m]; a4 += v * s_q[512 + m];
                }
                s_p2[0 * 256 + half * 128 + n] = a0;
                s_p2[1 * 256 + half * 128 + n] = a1;
                s_p2[2 * 256 + half * 128 + n] = a2;
                s_p2[3 * 256 + half * 128 + n] = a3;
                s_p2[4 * 256 + half * 128 + n] = a4;
            }
            __syncthreads();

            // per-head chain (warp h), shuffle-only reductions
            if (wid < 5) {
                int basei = (wid < 4) ? wid * 134 : 536;
                float beta = expf(s_instr[basei + 128]);
                float gg = 1.0f / (1.0f + expf(-s_instr[basei + 129]));
                float a0 = s_instr[basei + 130], a1 = s_instr[basei + 131], a2 = s_instr[basei + 132];
                float mxs = fmaxf(a0, fmaxf(a1, a2));
                float e0 = expf(a0 - mxs), e1 = expf(a1 - mxs), e2 = expf(a2 - mxs);
                float esi = 1.0f / (e0 + e1 + e2);
                float sh0 = e0 * esi, sh1 = e1 * esi, sh2 = e2 * esi;
                float xt = s_instr[basei + 133];
                float tpow = fmaxf(xt, 0.0f) + log1pf(expf(-fabsf(xt))) + 1.0f;

                float vv[4];
                float mx = -3.4e38f;
#pragma unroll
                for (int j = 0; j < 4; j++) {
                    int n = lane * 4 + j;
                    vv[j] = (s_p2[wid * 256 + n] + s_p2[wid * 256 + 128 + n]) * beta;
                    mx = fmaxf(mx, vv[j]);
                }
#pragma unroll
                for (int o = 16; o > 0; o >>= 1) mx = fmaxf(mx, __shfl_xor_sync(0xffffffffu, mx, o));
                float ee[4], se = 0.0f;
#pragma unroll
                for (int j = 0; j < 4; j++) { ee[j] = expf(vv[j] - mx); se += ee[j]; }
#pragma unroll
                for (int o = 16; o > 0; o >>= 1) se += __shfl_xor_sync(0xffffffffu, se, o);
                float sei = 1.0f / se;
#pragma unroll
                for (int j = 0; j < 4; j++) {
                    int n = lane * 4 + j;
                    float wold = s_w[wid * 128 + n];
                    s_wi[wid * 128 + n] = ee[j] * sei * gg + wold * (1.0f - gg);
                }
                __syncwarp();
                float pp[4], ps = 0.0f;
#pragma unroll
                for (int j = 0; j < 4; j++) {
                    int n = lane * 4 + j;
                    float ws = sh0 * s_wi[wid * 128 + ((n + 127) & 127)]
                             + sh1 * s_wi[wid * 128 + n]
                             + sh2 * s_wi[wid * 128 + ((n + 1) & 127)];
                    pp[j] = powf(ws, tpow);
                    ps += pp[j];
                }
#pragma unroll
                for (int o = 16; o > 0; o >>= 1) ps += __shfl_xor_sync(0xffffffffu, ps, o);
                float psi = 1.0f / (ps + 1e-12f);
#pragma unroll
                for (int j = 0; j < 4; j++) {
                    int n = lane * 4 + j;
                    s_w[wid * 128 + n] = pp[j] * psi;
                }
            }
            __syncthreads();

            // erase/add (W=1) + rv partials
            {
                int m = tid & 127, half = tid >> 7;
                float em = s_instr[670 + m];   // 536 + 134 + m
                float am = s_instr[798 + m];   // 536 + 262 + m
                float r0 = 0, r1 = 0, r2 = 0, r3 = 0;
                int n0 = half * 64;
#pragma unroll 4
                for (int n = n0; n < n0 + 64; n++) {
                    float wwn = s_w[512 + n];
                    float Mv = sM[n * 129 + m];
                    Mv = Mv * (1.0f - wwn * em) + wwn * am;
                    sM[n * 129 + m] = Mv;
                    r0 += Mv * s_w[n];       r1 += Mv * s_w[128 + n];
                    r2 += Mv * s_w[256 + n]; r3 += Mv * s_w[384 + n];
                }
                s_p2[0 * 256 + half * 128 + m] = r0;
                s_p2[1 * 256 + half * 128 + m] = r1;
                s_p2[2 * 256 + half * 128 + m] = r2;
                s_p2[3 * 256 + half * 128 + m] = r3;
            }
            __syncthreads();
            if (tid < 128) {
#pragma unroll
                for (int r = 0; r < 4; r++) {
                    float rv = s_p2[r * 256 + tid] + s_p2[r * 256 + 128 + tid];
                    __nv_bfloat16 h, l; bf16_split(rv, h, l);
                    g_rvh[e * 512 + r * 128 + tid] = h;
                    g_rvl[e * 512 + r * 128 + tid] = l;
                }
            }
        }
        grid_sync(++nsync * NB);
    }
}

// ---------------- launch ----------------
extern "C" void kernel_launch(void* const* d_in, const int* in_sizes, int n_in,
                              void* d_out, int out_size) {
    const float *x = nullptr, *Wc = nullptr, *bc = nullptr, *Wk = nullptr, *bk = nullptr;
    for (int i = 0; i < n_in; i++) {
        switch (in_sizes[i]) {
            case 128 * 64 * 512: x  = (const float*)d_in[i]; break;
            case 1024 * 512:     Wc = (const float*)d_in[i]; break;
            case 512:            bc = (const float*)d_in[i]; break;
            case 512 * 926:      Wk = (const float*)d_in[i]; break;
            case 926:            bk = (const float*)d_in[i]; break;
        }
    }

    // smem: 17152 floats (sM + s_w) + 1KB align slack + 55296B tiles
    const int SMEM = 17152 * 4 + 1024 + 55296;  // 124928 B
    cudaFuncSetAttribute(ntm_persistent, cudaFuncAttributeMaxDynamicSharedMemorySize, SMEM);

    prep_x_kernel<<<2048, 256>>>(x);
    prep_w_kernel<<<1024, 256>>>(Wc, Wk);
    ntm_persistent<<<128, 256, SMEM>>>(bc, bk, (float*)d_out);
}